// round 14
// baseline (speedup 1.0000x reference)
#include <cuda_runtime.h>
#include <cuda_fp16.h>
#include <cstdint>
#include <cstring>
#include <cstddef>

// ---------------- problem constants ----------------
#define TOKENS 4096
#define IN_F   4096
#define OUT_F  11008

// ---------------- GEMM tiling ----------------
#define TILE_M 128
#define TILE_N 128
#define TILE_K 64
#define KCHUNKS (IN_F / TILE_K)            // 64
#define STAGES 3
#define A_BYTES (TILE_M * TILE_K * 2)      // 16384
#define B_BYTES (TILE_N * TILE_K * 2)      // 16384
#define STG_BYTES (A_BYTES + B_BYTES)      // 32768
#define GEMM_SMEM (STAGES * STG_BYTES)     // 98304 -> 2 CTAs/SM

#define NBLK_ABS 1024                      // k_abssum grid; partials array size

// ---------------- device scratch (allocation-free) ----------------
__device__ __align__(16) __half g_wq[(size_t)OUT_F * IN_F];   // 90 MB ternary*scale fp16
__device__ __align__(16) __half g_xh[(size_t)TOKENS * IN_F];  // 32 MB x fp16
__device__ double g_partials[NBLK_ABS];    // per-block |W| sums (no init needed)

// ---------------- small kernels ----------------
// 8 floats per thread -> 16B store
__global__ void k_xconv(const float4* __restrict__ x) {
    int i = blockIdx.x * blockDim.x + threadIdx.x;
    float4 v0 = x[2 * i], v1 = x[2 * i + 1];
    __half2 h0 = __floats2half2_rn(v0.x, v0.y);
    __half2 h1 = __floats2half2_rn(v0.z, v0.w);
    __half2 h2 = __floats2half2_rn(v1.x, v1.y);
    __half2 h3 = __floats2half2_rn(v1.z, v1.w);
    uint4 u;
    memcpy(&u.x, &h0, 4); memcpy(&u.y, &h1, 4);
    memcpy(&u.z, &h2, 4); memcpy(&u.w, &h3, 4);
    reinterpret_cast<uint4*>(g_xh)[i] = u;
}

// each block writes its sum to g_partials[blockIdx.x] -- no atomic, no init kernel
__global__ void k_abssum(const float4* __restrict__ w, int n4) {
    float s = 0.f;
    int stride = gridDim.x * blockDim.x;
    for (int i = blockIdx.x * blockDim.x + threadIdx.x; i < n4; i += stride) {
        float4 v = w[i];
        s += fabsf(v.x) + fabsf(v.y) + fabsf(v.z) + fabsf(v.w);
    }
    #pragma unroll
    for (int o = 16; o > 0; o >>= 1) s += __shfl_xor_sync(0xFFFFFFFFu, s, o);
    __shared__ double ws[8];
    if ((threadIdx.x & 31) == 0) ws[threadIdx.x >> 5] = (double)s;
    __syncthreads();
    if (threadIdx.x == 0) {
        double t = 0.0;
        #pragma unroll
        for (int i = 0; i < 8; ++i) t += ws[i];
        g_partials[blockIdx.x] = t;
    }
}

// 8 weights per thread; block-local deterministic reduction of the 1024
// partials (8 KB, L2-resident) replaces the global atomic + init kernel
__global__ void k_quant(const float4* __restrict__ w, const float* __restrict__ scale) {
    __shared__ double wsum[8];
    __shared__ float s_alpha;
    {
        double p = 0.0;
        #pragma unroll
        for (int j = 0; j < 4; ++j) p += g_partials[threadIdx.x * 4 + j];
        #pragma unroll
        for (int o = 16; o > 0; o >>= 1) p += __shfl_xor_sync(0xFFFFFFFFu, p, o);
        if ((threadIdx.x & 31) == 0) wsum[threadIdx.x >> 5] = p;
        __syncthreads();
        if (threadIdx.x == 0) {
            double t = 0.0;
            #pragma unroll
            for (int k = 0; k < 8; ++k) t += wsum[k];
            s_alpha = (float)(t * (1.0 / ((double)OUT_F * (double)IN_F)));
        }
        __syncthreads();
    }
    const float alpha = s_alpha;

    int i = blockIdx.x * blockDim.x + threadIdx.x;   // one uint4 = 8 weights
    int row = i >> 9;                                // IN_F/8 = 512 uint4 per row
    float sc = __ldg(scale + row);
    float4 v0 = w[2 * i], v1 = w[2 * i + 1];
    float q0 = (v0.x > alpha) ? sc : ((v0.x < -alpha) ? -sc : 0.f);
    float q1 = (v0.y > alpha) ? sc : ((v0.y < -alpha) ? -sc : 0.f);
    float q2 = (v0.z > alpha) ? sc : ((v0.z < -alpha) ? -sc : 0.f);
    float q3 = (v0.w > alpha) ? sc : ((v0.w < -alpha) ? -sc : 0.f);
    float q4 = (v1.x > alpha) ? sc : ((v1.x < -alpha) ? -sc : 0.f);
    float q5 = (v1.y > alpha) ? sc : ((v1.y < -alpha) ? -sc : 0.f);
    float q6 = (v1.z > alpha) ? sc : ((v1.z < -alpha) ? -sc : 0.f);
    float q7 = (v1.w > alpha) ? sc : ((v1.w < -alpha) ? -sc : 0.f);
    __half2 h0 = __floats2half2_rn(q0, q1);
    __half2 h1 = __floats2half2_rn(q2, q3);
    __half2 h2 = __floats2half2_rn(q4, q5);
    __half2 h3 = __floats2half2_rn(q6, q7);
    uint4 u;
    memcpy(&u.x, &h0, 4); memcpy(&u.y, &h1, 4);
    memcpy(&u.z, &h2, 4); memcpy(&u.w, &h3, 4);
    reinterpret_cast<uint4*>(g_wq)[i] = u;
}

// ---------------- PTX helpers (base-PTX only) ----------------
__device__ __forceinline__ uint32_t smem_u32(const void* p) {
    uint32_t a;
    asm("{ .reg .u64 t; cvta.to.shared.u64 t, %1; cvt.u32.u64 %0, t; }" : "=r"(a) : "l"(p));
    return a;
}

#define CP_ASYNC16(dst, src) \
    asm volatile("cp.async.cg.shared.global [%0], [%1], 16;" :: "r"(dst), "l"(src) : "memory")
#define CP_COMMIT() asm volatile("cp.async.commit_group;" ::: "memory")
#define CP_WAIT1()  asm volatile("cp.async.wait_group 1;" ::: "memory")

#define LDMATRIX_X4(r0, r1, r2, r3, addr) \
    asm volatile("ldmatrix.sync.aligned.m8n8.x4.shared.b16 {%0,%1,%2,%3}, [%4];" \
        : "=r"(r0), "=r"(r1), "=r"(r2), "=r"(r3) : "r"(addr))

#define MMA_16816(c, a, b0, b1) \
    asm volatile("mma.sync.aligned.m16n8k16.row.col.f32.f16.f16.f32 " \
        "{%0,%1,%2,%3}, {%4,%5,%6,%7}, {%8,%9}, {%0,%1,%2,%3};" \
        : "+f"((c)[0]), "+f"((c)[1]), "+f"((c)[2]), "+f"((c)[3]) \
        : "r"((a)[0]), "r"((a)[1]), "r"((a)[2]), "r"((a)[3]), "r"(b0), "r"(b1))

// smem tile: 128 rows x 64 fp16 (128 B/row), XOR swizzle:
// off(row, kchunk) = row*128 + ((kchunk ^ (row&7)) << 4), kchunk = k/8
// 128 threads: 1024 16B chunks -> 8 per thread
__device__ __forceinline__ void load_tile_stage(
    uint32_t sdst, const __half* __restrict__ gsrc, int k0, int tid)
{
    #pragma unroll
    for (int r = 0; r < 8; ++r) {
        int c = tid + r * 128;
        int row = c >> 3, ch = c & 7;
        const __half* src = gsrc + (size_t)row * IN_F + k0 + ch * 8;
        uint32_t dst = sdst + row * 128 + ((ch ^ (row & 7)) << 4);
        CP_ASYNC16(dst, src);
    }
}

// ---------------- GEMM kernel (R7/R13 measured optimum -- frozen) ----------------
// 4 warps, warp tile 64x64; software-pipelined LDSM (double-buffered frags over ks)
__global__ void __launch_bounds__(128, 2)
k_gemm(float* __restrict__ out, const float* __restrict__ bias)
{
    extern __shared__ char smem[];
    const uint32_t sb = smem_u32(smem);
    const int tid = threadIdx.x;
    const int wid = tid >> 5, lane = tid & 31;
    const int warp_m = wid & 1;
    const int warp_n = wid >> 1;
    const int m0 = blockIdx.x * TILE_M;
    const int n0 = blockIdx.y * TILE_N;

    const __half* gA = g_xh + (size_t)m0 * IN_F;
    const __half* gB = g_wq + (size_t)n0 * IN_F;

    float acc[4][8][4];
    #pragma unroll
    for (int mi = 0; mi < 4; ++mi)
        #pragma unroll
        for (int nb = 0; nb < 8; ++nb)
            #pragma unroll
            for (int j = 0; j < 4; ++j) acc[mi][nb][j] = 0.f;

    load_tile_stage(sb, gA, 0, tid);
    load_tile_stage(sb + A_BYTES, gB, 0, tid);
    CP_COMMIT();
    load_tile_stage(sb + STG_BYTES, gA, TILE_K, tid);
    load_tile_stage(sb + STG_BYTES + A_BYTES, gB, TILE_K, tid);
    CP_COMMIT();

    // per-lane fragment rows
    int a_row[4], b_row[4];
    #pragma unroll
    for (int mi = 0; mi < 4; ++mi) a_row[mi] = warp_m * 64 + mi * 16 + (lane & 15);
    #pragma unroll
    for (int bi = 0; bi < 4; ++bi)
        b_row[bi] = warp_n * 64 + bi * 16 + (lane & 7) + ((lane >> 4) & 1) * 8;
    const int a_kc_off = (lane >> 4);
    const int b_kc_off = ((lane >> 3) & 1);

    #pragma unroll 1
    for (int i = 0; i < KCHUNKS; ++i) {
        CP_WAIT1();
        __syncthreads();

        if (i + 2 < KCHUNKS) {
            uint32_t s = sb + ((i + 2) % STAGES) * STG_BYTES;
            load_tile_stage(s, gA, (i + 2) * TILE_K, tid);
            load_tile_stage(s + A_BYTES, gB, (i + 2) * TILE_K, tid);
        }
        CP_COMMIT();

        const uint32_t sA = sb + (i % STAGES) * STG_BYTES;
        const uint32_t sB = sA + A_BYTES;

        // double-buffered fragments over the 4 ks-steps
        uint32_t a[2][4][4], b[2][4][4];

        // preload ks = 0 into buffer 0
        #pragma unroll
        for (int mi = 0; mi < 4; ++mi) {
            int kc = a_kc_off;
            uint32_t addr = sA + a_row[mi] * 128 + ((kc ^ (a_row[mi] & 7)) << 4);
            LDMATRIX_X4(a[0][mi][0], a[0][mi][1], a[0][mi][2], a[0][mi][3], addr);
        }
        #pragma unroll
        for (int bi = 0; bi < 4; ++bi) {
            int kc = b_kc_off;
            uint32_t addr = sB + b_row[bi] * 128 + ((kc ^ (b_row[bi] & 7)) << 4);
            LDMATRIX_X4(b[0][bi][0], b[0][bi][1], b[0][bi][2], b[0][bi][3], addr);
        }

        #pragma unroll
        for (int ks = 0; ks < 4; ++ks) {
            const int cur = ks & 1, nxt = cur ^ 1;
            // prefetch ks+1 before issuing MMAs of ks
            if (ks < 3) {
                #pragma unroll
                for (int mi = 0; mi < 4; ++mi) {
                    int kc = 2 * (ks + 1) + a_kc_off;
                    uint32_t addr = sA + a_row[mi] * 128 + ((kc ^ (a_row[mi] & 7)) << 4);
                    LDMATRIX_X4(a[nxt][mi][0], a[nxt][mi][1], a[nxt][mi][2], a[nxt][mi][3], addr);
                }
                #pragma unroll
                for (int bi = 0; bi < 4; ++bi) {
                    int kc = 2 * (ks + 1) + b_kc_off;
                    uint32_t addr = sB + b_row[bi] * 128 + ((kc ^ (b_row[bi] & 7)) << 4);
                    LDMATRIX_X4(b[nxt][bi][0], b[nxt][bi][1], b[nxt][bi][2], b[nxt][bi][3], addr);
                }
            }
            #pragma unroll
            for (int mi = 0; mi < 4; ++mi)
                #pragma unroll
                for (int nb = 0; nb < 8; ++nb) {
                    const int bi = nb >> 1, h = (nb & 1) * 2;
                    MMA_16816(acc[mi][nb], a[cur][mi], b[cur][bi][h], b[cur][bi][h + 1]);
                }
        }
    }

    // ---- epilogue ----
    const int g = lane >> 2, tig = lane & 3;
    #pragma unroll
    for (int nb = 0; nb < 8; ++nb) {
        const int col = n0 + warp_n * 64 + nb * 8 + tig * 2;
        const float2 bv = *reinterpret_cast<const float2*>(bias + col);
        #pragma unroll
        for (int mi = 0; mi < 4; ++mi) {
            const int r0 = m0 + warp_m * 64 + mi * 16 + g;
            float2 v0 = { acc[mi][nb][0] + bv.x, acc[mi][nb][1] + bv.y };
            float2 v1 = { acc[mi][nb][2] + bv.x, acc[mi][nb][3] + bv.y };
            *reinterpret_cast<float2*>(out + (size_t)r0 * OUT_F + col) = v0;
            *reinterpret_cast<float2*>(out + (size_t)(r0 + 8) * OUT_F + col) = v1;
        }
    }
}

// ---------------- host launch ----------------
extern "C" void kernel_launch(void* const* d_in, const int* in_sizes, int n_in,
                              void* d_out, int out_size)
{
    const float*  x     = (const float*)d_in[0];
    const float4* w4    = (const float4*)d_in[1];
    const float*  scale = (const float*)d_in[2];
    const float*  bias  = (const float*)d_in[3];
    float*        out   = (float*)d_out;

    cudaFuncSetAttribute(k_gemm, cudaFuncAttributeMaxDynamicSharedMemorySize, GEMM_SMEM);

    k_xconv<<<(TOKENS * IN_F / 8) / 256, 256>>>((const float4*)x);
    k_abssum<<<NBLK_ABS, 256>>>(w4, OUT_F * IN_F / 4);
    k_quant<<<(OUT_F * IN_F / 8) / 256, 256>>>(w4, scale);
    k_gemm<<<dim3(TOKENS / TILE_M, OUT_F / TILE_N, 1), 128, GEMM_SMEM>>>(out, bias);
}

// round 15
// speedup vs baseline: 1.2208x; 1.2208x over previous
#include <cuda_runtime.h>
#include <cuda_fp16.h>
#include <cstdint>
#include <cstring>
#include <cstddef>

// ---------------- problem constants ----------------
#define TOKENS 4096
#define IN_F   4096
#define OUT_F  11008

// ---------------- GEMM tiling ----------------
#define TILE_M 128
#define TILE_N 128
#define TILE_K 64
#define KCHUNKS (IN_F / TILE_K)            // 64
#define STAGES 3
#define A_BYTES (TILE_M * TILE_K * 2)      // 16384
#define B_BYTES (TILE_N * TILE_K * 2)      // 16384
#define STG_BYTES (A_BYTES + B_BYTES)      // 32768
#define GEMM_SMEM (STAGES * STG_BYTES)     // 98304 -> 2 CTAs/SM

// ---------------- device scratch (allocation-free) ----------------
__device__ __align__(16) __half g_wq[(size_t)OUT_F * IN_F];   // 90 MB ternary*scale fp16
__device__ __align__(16) __half g_xh[(size_t)TOKENS * IN_F];  // 32 MB x fp16
__device__ double g_abs_sum;

// ---------------- small kernels (R13 verbatim) ----------------
__global__ void k_init() { g_abs_sum = 0.0; }

__global__ void k_abssum(const float4* __restrict__ w, int n4) {
    float s = 0.f;
    int stride = gridDim.x * blockDim.x;
    for (int i = blockIdx.x * blockDim.x + threadIdx.x; i < n4; i += stride) {
        float4 v = w[i];
        s += fabsf(v.x) + fabsf(v.y) + fabsf(v.z) + fabsf(v.w);
    }
    #pragma unroll
    for (int o = 16; o > 0; o >>= 1) s += __shfl_xor_sync(0xFFFFFFFFu, s, o);
    __shared__ double ws[8];
    if ((threadIdx.x & 31) == 0) ws[threadIdx.x >> 5] = (double)s;
    __syncthreads();
    if (threadIdx.x == 0) {
        double t = 0.0;
        #pragma unroll
        for (int i = 0; i < 8; ++i) t += ws[i];
        atomicAdd(&g_abs_sum, t);
    }
}

// 8 weights per thread: 2x float4 load, 1x uint4 (16B) store
__global__ void k_quant(const float4* __restrict__ w, const float* __restrict__ scale) {
    int i = blockIdx.x * blockDim.x + threadIdx.x;   // one uint4 = 8 weights
    float alpha = (float)(g_abs_sum * (1.0 / ((double)OUT_F * (double)IN_F)));
    int row = i >> 9;                                // IN_F/8 = 512 uint4 per row
    float sc = __ldg(scale + row);
    float4 v0 = w[2 * i], v1 = w[2 * i + 1];
    float q0 = (v0.x > alpha) ? sc : ((v0.x < -alpha) ? -sc : 0.f);
    float q1 = (v0.y > alpha) ? sc : ((v0.y < -alpha) ? -sc : 0.f);
    float q2 = (v0.z > alpha) ? sc : ((v0.z < -alpha) ? -sc : 0.f);
    float q3 = (v0.w > alpha) ? sc : ((v0.w < -alpha) ? -sc : 0.f);
    float q4 = (v1.x > alpha) ? sc : ((v1.x < -alpha) ? -sc : 0.f);
    float q5 = (v1.y > alpha) ? sc : ((v1.y < -alpha) ? -sc : 0.f);
    float q6 = (v1.z > alpha) ? sc : ((v1.z < -alpha) ? -sc : 0.f);
    float q7 = (v1.w > alpha) ? sc : ((v1.w < -alpha) ? -sc : 0.f);
    __half2 h0 = __floats2half2_rn(q0, q1);
    __half2 h1 = __floats2half2_rn(q2, q3);
    __half2 h2 = __floats2half2_rn(q4, q5);
    __half2 h3 = __floats2half2_rn(q6, q7);
    uint4 u;
    memcpy(&u.x, &h0, 4); memcpy(&u.y, &h1, 4);
    memcpy(&u.z, &h2, 4); memcpy(&u.w, &h3, 4);
    reinterpret_cast<uint4*>(g_wq)[i] = u;
}

// 8 floats per thread -> 16B store
__global__ void k_xconv(const float4* __restrict__ x) {
    int i = blockIdx.x * blockDim.x + threadIdx.x;
    float4 v0 = x[2 * i], v1 = x[2 * i + 1];
    __half2 h0 = __floats2half2_rn(v0.x, v0.y);
    __half2 h1 = __floats2half2_rn(v0.z, v0.w);
    __half2 h2 = __floats2half2_rn(v1.x, v1.y);
    __half2 h3 = __floats2half2_rn(v1.z, v1.w);
    uint4 u;
    memcpy(&u.x, &h0, 4); memcpy(&u.y, &h1, 4);
    memcpy(&u.z, &h2, 4); memcpy(&u.w, &h3, 4);
    reinterpret_cast<uint4*>(g_xh)[i] = u;
}

// ---------------- PTX helpers (base-PTX only) ----------------
__device__ __forceinline__ uint32_t smem_u32(const void* p) {
    uint32_t a;
    asm("{ .reg .u64 t; cvta.to.shared.u64 t, %1; cvt.u32.u64 %0, t; }" : "=r"(a) : "l"(p));
    return a;
}

#define CP_ASYNC16(dst, src) \
    asm volatile("cp.async.cg.shared.global [%0], [%1], 16;" :: "r"(dst), "l"(src) : "memory")
#define CP_COMMIT() asm volatile("cp.async.commit_group;" ::: "memory")
#define CP_WAIT1()  asm volatile("cp.async.wait_group 1;" ::: "memory")

#define LDMATRIX_X4(r0, r1, r2, r3, addr) \
    asm volatile("ldmatrix.sync.aligned.m8n8.x4.shared.b16 {%0,%1,%2,%3}, [%4];" \
        : "=r"(r0), "=r"(r1), "=r"(r2), "=r"(r3) : "r"(addr))

#define MMA_16816(c, a, b0, b1) \
    asm volatile("mma.sync.aligned.m16n8k16.row.col.f32.f16.f16.f32 " \
        "{%0,%1,%2,%3}, {%4,%5,%6,%7}, {%8,%9}, {%0,%1,%2,%3};" \
        : "+f"((c)[0]), "+f"((c)[1]), "+f"((c)[2]), "+f"((c)[3]) \
        : "r"((a)[0]), "r"((a)[1]), "r"((a)[2]), "r"((a)[3]), "r"(b0), "r"(b1))

// smem tile: 128 rows x 64 fp16 (128 B/row), XOR swizzle:
// off(row, kchunk) = row*128 + ((kchunk ^ (row&7)) << 4), kchunk = k/8
// 128 threads: 1024 16B chunks -> 8 per thread
__device__ __forceinline__ void load_tile_stage(
    uint32_t sdst, const __half* __restrict__ gsrc, int k0, int tid)
{
    #pragma unroll
    for (int r = 0; r < 8; ++r) {
        int c = tid + r * 128;
        int row = c >> 3, ch = c & 7;
        const __half* src = gsrc + (size_t)row * IN_F + k0 + ch * 8;
        uint32_t dst = sdst + row * 128 + ((ch ^ (row & 7)) << 4);
        CP_ASYNC16(dst, src);
    }
}

// ---------------- GEMM kernel ----------------
// R13 structure with ONE change: per chunk, the ks=0 fragment LDSM preloads
// issue BEFORE the next-stage cp.async batch, so the first MMA is not stuck
// behind ~128 cycles of LDGSTS issue. Commit-group ordering is unchanged:
// the group for chunk i+2 is still committed within iteration i.
__global__ void __launch_bounds__(128, 2)
k_gemm(float* __restrict__ out, const float* __restrict__ bias)
{
    extern __shared__ char smem[];
    const uint32_t sb = smem_u32(smem);
    const int tid = threadIdx.x;
    const int wid = tid >> 5, lane = tid & 31;
    const int warp_m = wid & 1;
    const int warp_n = wid >> 1;
    const int m0 = blockIdx.x * TILE_M;
    const int n0 = blockIdx.y * TILE_N;

    const __half* gA = g_xh + (size_t)m0 * IN_F;
    const __half* gB = g_wq + (size_t)n0 * IN_F;

    float acc[4][8][4];
    #pragma unroll
    for (int mi = 0; mi < 4; ++mi)
        #pragma unroll
        for (int nb = 0; nb < 8; ++nb)
            #pragma unroll
            for (int j = 0; j < 4; ++j) acc[mi][nb][j] = 0.f;

    load_tile_stage(sb, gA, 0, tid);
    load_tile_stage(sb + A_BYTES, gB, 0, tid);
    CP_COMMIT();
    load_tile_stage(sb + STG_BYTES, gA, TILE_K, tid);
    load_tile_stage(sb + STG_BYTES + A_BYTES, gB, TILE_K, tid);
    CP_COMMIT();

    // per-lane fragment rows
    int a_row[4], b_row[4];
    #pragma unroll
    for (int mi = 0; mi < 4; ++mi) a_row[mi] = warp_m * 64 + mi * 16 + (lane & 15);
    #pragma unroll
    for (int bi = 0; bi < 4; ++bi)
        b_row[bi] = warp_n * 64 + bi * 16 + (lane & 7) + ((lane >> 4) & 1) * 8;
    const int a_kc_off = (lane >> 4);
    const int b_kc_off = ((lane >> 3) & 1);

    #pragma unroll 1
    for (int i = 0; i < KCHUNKS; ++i) {
        CP_WAIT1();
        __syncthreads();

        const uint32_t sA = sb + (i % STAGES) * STG_BYTES;
        const uint32_t sB = sA + A_BYTES;

        // double-buffered fragments over the 4 ks-steps
        uint32_t a[2][4][4], b[2][4][4];

        // preload ks = 0 FIRST (critical path to the first MMA)
        #pragma unroll
        for (int mi = 0; mi < 4; ++mi) {
            int kc = a_kc_off;
            uint32_t addr = sA + a_row[mi] * 128 + ((kc ^ (a_row[mi] & 7)) << 4);
            LDMATRIX_X4(a[0][mi][0], a[0][mi][1], a[0][mi][2], a[0][mi][3], addr);
        }
        #pragma unroll
        for (int bi = 0; bi < 4; ++bi) {
            int kc = b_kc_off;
            uint32_t addr = sB + b_row[bi] * 128 + ((kc ^ (b_row[bi] & 7)) << 4);
            LDMATRIX_X4(b[0][bi][0], b[0][bi][1], b[0][bi][2], b[0][bi][3], addr);
        }

        // now issue the next-stage global loads (off the first-MMA critical path)
        if (i + 2 < KCHUNKS) {
            uint32_t s = sb + ((i + 2) % STAGES) * STG_BYTES;
            load_tile_stage(s, gA, (i + 2) * TILE_K, tid);
            load_tile_stage(s + A_BYTES, gB, (i + 2) * TILE_K, tid);
        }
        CP_COMMIT();

        #pragma unroll
        for (int ks = 0; ks < 4; ++ks) {
            const int cur = ks & 1, nxt = cur ^ 1;
            // prefetch ks+1 before issuing MMAs of ks
            if (ks < 3) {
                #pragma unroll
                for (int mi = 0; mi < 4; ++mi) {
                    int kc = 2 * (ks + 1) + a_kc_off;
                    uint32_t addr = sA + a_row[mi] * 128 + ((kc ^ (a_row[mi] & 7)) << 4);
                    LDMATRIX_X4(a[nxt][mi][0], a[nxt][mi][1], a[nxt][mi][2], a[nxt][mi][3], addr);
                }
                #pragma unroll
                for (int bi = 0; bi < 4; ++bi) {
                    int kc = 2 * (ks + 1) + b_kc_off;
                    uint32_t addr = sB + b_row[bi] * 128 + ((kc ^ (b_row[bi] & 7)) << 4);
                    LDMATRIX_X4(b[nxt][bi][0], b[nxt][bi][1], b[nxt][bi][2], b[nxt][bi][3], addr);
                }
            }
            #pragma unroll
            for (int mi = 0; mi < 4; ++mi)
                #pragma unroll
                for (int nb = 0; nb < 8; ++nb) {
                    const int bi = nb >> 1, h = (nb & 1) * 2;
                    MMA_16816(acc[mi][nb], a[cur][mi], b[cur][bi][h], b[cur][bi][h + 1]);
                }
        }
    }

    // ---- epilogue ----
    const int g = lane >> 2, tig = lane & 3;
    #pragma unroll
    for (int nb = 0; nb < 8; ++nb) {
        const int col = n0 + warp_n * 64 + nb * 8 + tig * 2;
        const float2 bv = *reinterpret_cast<const float2*>(bias + col);
        #pragma unroll
        for (int mi = 0; mi < 4; ++mi) {
            const int r0 = m0 + warp_m * 64 + mi * 16 + g;
            float2 v0 = { acc[mi][nb][0] + bv.x, acc[mi][nb][1] + bv.y };
            float2 v1 = { acc[mi][nb][2] + bv.x, acc[mi][nb][3] + bv.y };
            *reinterpret_cast<float2*>(out + (size_t)r0 * OUT_F + col) = v0;
            *reinterpret_cast<float2*>(out + (size_t)(r0 + 8) * OUT_F + col) = v1;
        }
    }
}

// ---------------- host launch ----------------
extern "C" void kernel_launch(void* const* d_in, const int* in_sizes, int n_in,
                              void* d_out, int out_size)
{
    const float*  x     = (const float*)d_in[0];
    const float4* w4    = (const float4*)d_in[1];
    const float*  scale = (const float*)d_in[2];
    const float*  bias  = (const float*)d_in[3];
    float*        out   = (float*)d_out;

    cudaFuncSetAttribute(k_gemm, cudaFuncAttributeMaxDynamicSharedMemorySize, GEMM_SMEM);

    k_init<<<1, 1>>>();
    k_xconv<<<(TOKENS * IN_F / 8) / 256, 256>>>((const float4*)x);
    k_abssum<<<1024, 256>>>(w4, OUT_F * IN_F / 4);
    k_quant<<<(OUT_F * IN_F / 8) / 256, 256>>>(w4, scale);
    k_gemm<<<dim3(TOKENS / TILE_M, OUT_F / TILE_N, 1), 128, GEMM_SMEM>>>(out, bias);
}